// round 8
// baseline (speedup 1.0000x reference)
#include <cuda_runtime.h>
#include <cuda_fp16.h>
#include <cstdint>

// ---------------------------------------------------------------------------
// R8 (= R7 resubmit after infra failure): conv1 HMMA with ALL-resident smem
//     (A: 4 img rows both split terms, W: all 9 taps) -> ONE build + ONE
//     barrier per CTA, then a pure LDSM/HMMA stream. SW128 swizzle.
//     conv2 = proven R4 fp32 FFMA2 kernel.
// ---------------------------------------------------------------------------

#define IMG   256
#define NB    8
#define CIN   64

__device__ float  g_h[NB * CIN * IMG * IMG];
__device__ __half g_w1h[9 * 64 * 64];          // swizzled: tap*8192B + swz(c*128+oc*2)
__device__ float  g_w2q[CIN * 9 * 4];

__device__ __forceinline__ uint32_t smem_u32(const void* p) {
    uint32_t a;
    asm("{ .reg .u64 t; cvta.to.shared.u64 t, %1; cvt.u32.u64 %0, t; }"
        : "=r"(a) : "l"(p));
    return a;
}
__device__ __forceinline__ void ldsm4(uint32_t* r, uint32_t addr) {
    asm volatile("ldmatrix.sync.aligned.m8n8.x4.shared.b16 {%0,%1,%2,%3}, [%4];"
        : "=r"(r[0]), "=r"(r[1]), "=r"(r[2]), "=r"(r[3]) : "r"(addr));
}
__device__ __forceinline__ void ldsm2t(uint32_t& r0, uint32_t& r1, uint32_t addr) {
    asm volatile("ldmatrix.sync.aligned.m8n8.x2.trans.shared.b16 {%0,%1}, [%2];"
        : "=r"(r0), "=r"(r1) : "r"(addr));
}
__device__ __forceinline__ void mma16816(float* c, const uint32_t* a, const uint32_t* b) {
    asm volatile("mma.sync.aligned.m16n8k16.row.col.f32.f16.f16.f32 "
        "{%0,%1,%2,%3}, {%4,%5,%6,%7}, {%8,%9}, {%0,%1,%2,%3};"
        : "+f"(c[0]), "+f"(c[1]), "+f"(c[2]), "+f"(c[3])
        : "r"(a[0]), "r"(a[1]), "r"(a[2]), "r"(a[3]), "r"(b[0]), "r"(b[1]));
}

// smem layout (dynamic):
#define A_IR    16640u                 // 130 rows * 128 B
#define A_TERM  (4u * A_IR)            // 66560
#define SM_W    (2u * A_TERM)          // 133120
#define W_BYTES 73728u
#define SM_P    (SM_W + W_BYTES)       // 206848
#define SMEM1   (SM_P + 1024u)         // 207872

// ---------------- prequant (one-shot) ---------------------------------------
__global__ void prequant_kernel(const float* __restrict__ w1,
                                const float* __restrict__ sw1,
                                const float* __restrict__ w2,
                                const float* __restrict__ sw2)
{
    int idx = blockIdx.x * 256 + threadIdx.x;
    if (idx < 9 * 64 * 64) {
        int oc  = idx & 63;
        int c   = (idx >> 6) & 63;
        int tap = idx >> 12;
        float w = w1[(oc * 64 + c) * 9 + tap];
        float s = sw1[oc];
        float q = rintf(w / s);
        q = fminf(fmaxf(q, -64.f), 63.f);
        uint32_t off = (uint32_t)tap * 8192u + (uint32_t)c * 128u
                     + (((uint32_t)oc * 2u) ^ (((uint32_t)(c & 7)) << 4));
        *(__half*)((char*)g_w1h + off) = __float2half_rn(q);   // exact int
    } else if (idx < 9 * 64 * 64 + 64 * 9 * 4) {
        int j  = idx - 9 * 64 * 64;
        int oc = j & 3;
        int k  = j >> 2;
        int c  = k / 9;
        int kk = k - c * 9;
        float v = 0.f;
        if (oc < 3) {
            float w = w2[(oc * CIN + c) * 9 + kk];
            float s = sw2[oc];
            float q = rintf(w / s);
            q = fminf(fmaxf(q, -64.f), 63.f);
            v = q * s;
        }
        g_w2q[j] = v;
    }
}

// ---------------- conv1: HMMA, all-resident ---------------------------------
// CTA: 2 output rows (y0, y0+1) x 128 px x 64 oc. 256 thr = 8 warps.
// Warp: dy=(warp&3)>>1, jb=(warp&1)*64, ncol=(warp>>2)*32 -> 64px x 32oc.
__global__ __launch_bounds__(256, 1)
void conv1_mma_kernel(const float* __restrict__ x,
                      const float* __restrict__ sw1,
                      const float* __restrict__ b1,
                      const float* __restrict__ alpha1,
                      const float* __restrict__ sa1)
{
    extern __shared__ unsigned char sm[];
    const uint32_t sa_base = smem_u32(sm);
    const uint32_t sw_base = sa_base + SM_W;
    float* s_prm = (float*)(sm + SM_P);

    const int tid  = threadIdx.x;
    const int lane = tid & 31;
    const int warp = tid >> 5;
    const int dy   = (warp & 3) >> 1;
    const int jb   = (warp & 1) * 64;
    const int ncol = (warp >> 2) * 32;

    const int bid = blockIdx.x;           // 8n * 128yg * 2xt = 2048
    const int x0  = (bid & 1) * 128;
    const int y0  = ((bid >> 1) & 127) * 2;
    const int n   = bid >> 8;

    // ---- params ----
    if (tid < 256) {
        int a = tid >> 6, oc = tid & 63;
        const float* src = (a == 0) ? sw1 : (a == 1) ? b1 : (a == 2) ? alpha1 : sa1;
        s_prm[a * 64 + oc] = src[oc];
    }
    // ---- W: all 9 taps, pre-swizzled, straight copy ----
    {
        const uint4* src = reinterpret_cast<const uint4*>(g_w1h);
        uint4* dst = reinterpret_cast<uint4*>(sm + SM_W);
        #pragma unroll
        for (int i = 0; i < 18; ++i) dst[tid + i * 256] = src[tid + i * 256];
    }
    // ---- A: 4 image rows, exact fp16 2-term split ----
    for (int idx = tid; idx < 4 * 130 * 64; idx += 256) {
        int j    = idx % 130;
        int rest = idx / 130;
        int ir   = rest & 3;
        int c    = rest >> 2;
        int gy   = y0 + ir - 1;
        int gx   = x0 - 1 + j;
        float v = 0.f;
        if ((unsigned)gy < 256u && (unsigned)gx < 256u)
            v = x[(((n * 64 + c) * 256 + gy) << 8) + gx];
        __half hi = __float2half_rn(v);
        __half lo = __float2half_rn(v - __half2float(hi));
        uint32_t off = (uint32_t)ir * A_IR + (uint32_t)j * 128u
                     + (((uint32_t)c * 2u) ^ (((uint32_t)(j & 7)) << 4));
        *(__half*)(sm + off)          = hi;
        *(__half*)(sm + A_TERM + off) = lo;
    }
    __syncthreads();     // the ONLY barrier before the epilogue

    float acc[4][4][4];
    #pragma unroll
    for (int a = 0; a < 4; ++a)
        #pragma unroll
        for (int b = 0; b < 4; ++b)
            #pragma unroll
            for (int c = 0; c < 4; ++c) acc[a][b][c] = 0.f;

    const uint32_t arow  = lane & 15;
    const uint32_t ahalf = (lane >> 4) * 16;

    #pragma unroll 1
    for (int kh = 0; kh < 3; ++kh) {
        #pragma unroll
        for (int kw = 0; kw < 3; ++kw) {
            // ---- B fragments for this tap ----
            uint32_t bf[4][4][2];
            #pragma unroll
            for (int k = 0; k < 4; ++k)
                #pragma unroll
                for (int nb = 0; nb < 4; ++nb) {
                    uint32_t row = k * 16 + arow;
                    ldsm2t(bf[k][nb][0], bf[k][nb][1],
                           sw_base + (uint32_t)(kh * 3 + kw) * 8192u + row * 128u
                                   + (((uint32_t)(ncol + nb * 8) * 2u) ^ ((row & 7u) << 4)));
                }
            // ---- A fragments + MMAs (both split terms into same acc) ----
            #pragma unroll
            for (int t = 0; t < 2; ++t) {
                #pragma unroll
                for (int mb = 0; mb < 4; ++mb) {
                    uint32_t row  = (uint32_t)(jb + mb * 16 + kw) + arow;
                    uint32_t base = sa_base + (uint32_t)t * A_TERM
                                  + (uint32_t)(dy + kh) * A_IR + row * 128u;
                    uint32_t xr   = (row & 7u) << 4;
                    uint32_t af[4][4];
                    #pragma unroll
                    for (int k = 0; k < 4; ++k)
                        ldsm4(af[k], base + ((ahalf + (uint32_t)k * 32u) ^ xr));
                    #pragma unroll
                    for (int k = 0; k < 4; ++k)
                        #pragma unroll
                        for (int nb = 0; nb < 4; ++nb)
                            mma16816(acc[mb][nb], af[k], bf[k][nb]);
                }
            }
        }
    }

    // ---- epilogue: scale + bias + PReLU + act fake-quant -> g_h ------------
    const int gy = y0 + dy;
    #pragma unroll
    for (int mb = 0; mb < 4; ++mb)
        #pragma unroll
        for (int nb = 0; nb < 4; ++nb)
            #pragma unroll
            for (int rg = 0; rg < 4; ++rg) {
                int j  = jb + mb * 16 + (lane >> 2) + (rg >> 1) * 8;
                int oc = ncol + nb * 8 + ((lane & 3) << 1) + (rg & 1);
                float v  = acc[mb][nb][rg] * s_prm[oc] + s_prm[64 + oc];
                float pv = (v >= 0.f) ? v : s_prm[128 + oc] * v;
                float ss = s_prm[192 + oc];
                float q  = rintf(pv / ss);
                q = fminf(fmaxf(q, -64.f), 63.f);
                g_h[(((n * 64 + oc) * 256 + gy) << 8) + x0 + j] = q * ss;
            }
}

// ---------------- conv2: fp32 FFMA2 (proven R4 kernel, unchanged) -----------
#define TH2   8
#define T2W   128
#define CC2   4
#define P2R   10
#define P2CW  130
#define P2W   131

__global__ __launch_bounds__(128, 6)
void conv2_kernel(const float* __restrict__ b2,
                  const float* __restrict__ alpha2,
                  const float* __restrict__ sa2,
                  float* __restrict__ out)
{
    __shared__ __align__(16) float s_in[CC2 * P2R * P2W];
    __shared__ __align__(16) float s_w2[CC2 * 9 * 4];

    const int tid = threadIdx.x;
    const int bid = blockIdx.x;
    const int tx  = bid & 1;
    const int ty  = (bid >> 1) & 31;
    const int n   = bid >> 6;
    const int x0  = tx * T2W;
    const int y0  = ty * TH2;

    const int r    = tid & 7;
    const int g    = (tid >> 3) & 3;
    const int warp = tid >> 5;
    const int cb   = warp * 32 + g * 8;

    unsigned long long acc[2][8];
    #pragma unroll
    for (int i = 0; i < 2; ++i)
        #pragma unroll
        for (int j = 0; j < 8; ++j) acc[i][j] = 0ULL;

    for (int c0 = 0; c0 < CIN; c0 += CC2) {
        __syncthreads();
        for (int idx = tid; idx < CC2 * P2R * P2CW; idx += 128) {
            int c   = idx / (P2R * P2CW);
            int rem = idx - c * (P2R * P2CW);
            int row = rem / P2CW;
            int col = rem - row * P2CW;
            int gy  = y0 + row - 1;
            int gx  = x0 + col - 1;
            float v = 0.f;
            if ((unsigned)gy < 256u && (unsigned)gx < 256u)
                v = g_h[(((n * CIN + c0 + c) * 256 + gy) << 8) + gx];
            s_in[(c * P2R + row) * P2W + col] = v;
        }
        for (int idx = tid; idx < CC2 * 9 * 4; idx += 128)
            s_w2[idx] = g_w2q[c0 * 9 * 4 + idx];
        __syncthreads();

        #pragma unroll 1
        for (int c = 0; c < CC2; ++c) {
            #pragma unroll
            for (int kh = 0; kh < 3; ++kh) {
                const float* rowp = &s_in[(c * P2R + r + kh) * P2W + cb];
                unsigned long long v2[10];
                #pragma unroll
                for (int i = 0; i < 10; ++i) {
                    unsigned int u = __float_as_uint(rowp[i]);
                    asm("mov.b64 %0, {%1, %1};" : "=l"(v2[i]) : "r"(u));
                }
                #pragma unroll
                for (int kw = 0; kw < 3; ++kw) {
                    const unsigned long long* wp = (const unsigned long long*)
                        &s_w2[(c * 9 + kh * 3 + kw) << 2];
                    unsigned long long w0 = wp[0];
                    unsigned long long w1 = wp[1];
                    #pragma unroll
                    for (int px = 0; px < 8; ++px) {
                        asm("fma.rn.f32x2 %0, %1, %2, %0;"
                            : "+l"(acc[0][px]) : "l"(w0), "l"(v2[px + kw]));
                        asm("fma.rn.f32x2 %0, %1, %2, %0;"
                            : "+l"(acc[1][px]) : "l"(w1), "l"(v2[px + kw]));
                    }
                }
            }
        }
    }

    const int gy = y0 + r;
    const int gx = x0 + cb;
    #pragma unroll
    for (int cp = 0; cp < 2; ++cp) {
        float lo[8], hi[8];
        #pragma unroll
        for (int px = 0; px < 8; ++px) {
            unsigned int a, b;
            asm("mov.b64 {%0, %1}, %2;" : "=r"(a), "=r"(b) : "l"(acc[cp][px]));
            lo[px] = __uint_as_float(a);
            hi[px] = __uint_as_float(b);
        }
        #pragma unroll
        for (int half = 0; half < 2; ++half) {
            int oc = (cp << 1) + half;
            if (oc >= 3) continue;
            const float* v = half ? hi : lo;
            float bb = b2[oc], aa = alpha2[oc], ss = sa2[oc];
            float o[8];
            #pragma unroll
            for (int i = 0; i < 8; ++i) {
                float yv = v[i] + bb;
                float pv = (yv >= 0.f) ? yv : aa * yv;
                float q = rintf(pv / ss);
                q = fminf(fmaxf(q, -64.f), 63.f);
                o[i] = q * ss;
            }
            float4* p4 = reinterpret_cast<float4*>(
                &out[(((n * 3 + oc) * 256 + gy) << 8) + gx]);
            p4[0] = make_float4(o[0], o[1], o[2], o[3]);
            p4[1] = make_float4(o[4], o[5], o[6], o[7]);
        }
    }
}

// ---------------------------------------------------------------------------
extern "C" void kernel_launch(void* const* d_in, const int* in_sizes, int n_in,
                              void* d_out, int out_size)
{
    const float* x      = (const float*)d_in[0];
    const float* w1     = (const float*)d_in[1];
    const float* b1     = (const float*)d_in[2];
    const float* w2     = (const float*)d_in[3];
    const float* b2     = (const float*)d_in[4];
    const float* alpha1 = (const float*)d_in[5];
    const float* alpha2 = (const float*)d_in[6];
    const float* sw1    = (const float*)d_in[7];
    const float* sw2    = (const float*)d_in[8];
    const float* sa1    = (const float*)d_in[9];
    const float* sa2    = (const float*)d_in[10];
    float* out = (float*)d_out;

    cudaFuncSetAttribute(conv1_mma_kernel,
                         cudaFuncAttributeMaxDynamicSharedMemorySize, SMEM1);

    prequant_kernel<<<(9 * 64 * 64 + 64 * 9 * 4 + 255) / 256, 256>>>(w1, sw1, w2, sw2);
    conv1_mma_kernel<<<NB * 128 * 2, 256, SMEM1>>>(x, sw1, b1, alpha1, sa1);
    conv2_kernel<<<NB * 32 * 2, 128>>>(b2, alpha2, sa2, out);
}

// round 9
// speedup vs baseline: 1.1676x; 1.1676x over previous
#include <cuda_runtime.h>
#include <cuda_fp16.h>
#include <cstdint>

// ---------------------------------------------------------------------------
// R9: conv1 HMMA, occ-2 restored (106.5KB smem), A built once (1 barrier),
//     W register-prefetch pipeline (2 barriers/tap, LDG hidden under MMAs).
//     conv2 = proven R4 fp32 FFMA2 kernel.
// ---------------------------------------------------------------------------

#define IMG   256
#define NB    8
#define CIN   64

__device__ float  g_h[NB * CIN * IMG * IMG];
__device__ __half g_w1h[9 * 64 * 64];          // swizzled: tap*8192B + c*128 + (oc*2 ^ ((c&7)<<4))
__device__ float  g_w2q[CIN * 9 * 4];

__device__ __forceinline__ uint32_t smem_u32(const void* p) {
    uint32_t a;
    asm("{ .reg .u64 t; cvta.to.shared.u64 t, %1; cvt.u32.u64 %0, t; }"
        : "=r"(a) : "l"(p));
    return a;
}
__device__ __forceinline__ void ldsm4(uint32_t* r, uint32_t addr) {
    asm volatile("ldmatrix.sync.aligned.m8n8.x4.shared.b16 {%0,%1,%2,%3}, [%4];"
        : "=r"(r[0]), "=r"(r[1]), "=r"(r[2]), "=r"(r[3]) : "r"(addr));
}
__device__ __forceinline__ void ldsm2t(uint32_t& r0, uint32_t& r1, uint32_t addr) {
    asm volatile("ldmatrix.sync.aligned.m8n8.x2.trans.shared.b16 {%0,%1}, [%2];"
        : "=r"(r0), "=r"(r1) : "r"(addr));
}
__device__ __forceinline__ void mma16816(float* c, const uint32_t* a, const uint32_t* b) {
    asm volatile("mma.sync.aligned.m16n8k16.row.col.f32.f16.f16.f32 "
        "{%0,%1,%2,%3}, {%4,%5,%6,%7}, {%8,%9}, {%0,%1,%2,%3};"
        : "+f"(c[0]), "+f"(c[1]), "+f"(c[2]), "+f"(c[3])
        : "r"(a[0]), "r"(a[1]), "r"(a[2]), "r"(a[3]), "r"(b[0]), "r"(b[1]));
}

// smem layout (dynamic):
#define A_IR    16640u                 // 130 px-rows * 128 B
#define A_TERM3 (3u * A_IR)            // 49920 (3 image rows)
#define SM_W    (2u * A_TERM3)         // 99840
#define SM_P    (SM_W + 8192u)         // 108032
#define SMEM1   (SM_P + 1024u)         // 109056  -> occ 2 (218KB/SM)

// ---------------- prequant (one-shot) ---------------------------------------
__global__ void prequant_kernel(const float* __restrict__ w1,
                                const float* __restrict__ sw1,
                                const float* __restrict__ w2,
                                const float* __restrict__ sw2)
{
    int idx = blockIdx.x * 256 + threadIdx.x;
    if (idx < 9 * 64 * 64) {
        int oc  = idx & 63;
        int c   = (idx >> 6) & 63;
        int tap = idx >> 12;
        float w = w1[(oc * 64 + c) * 9 + tap];
        float s = sw1[oc];
        float q = rintf(w / s);
        q = fminf(fmaxf(q, -64.f), 63.f);
        uint32_t off = (uint32_t)tap * 8192u + (uint32_t)c * 128u
                     + (((uint32_t)oc * 2u) ^ (((uint32_t)(c & 7)) << 4));
        *(__half*)((char*)g_w1h + off) = __float2half_rn(q);   // exact int
    } else if (idx < 9 * 64 * 64 + 64 * 9 * 4) {
        int j  = idx - 9 * 64 * 64;
        int oc = j & 3;
        int k  = j >> 2;
        int c  = k / 9;
        int kk = k - c * 9;
        float v = 0.f;
        if (oc < 3) {
            float w = w2[(oc * CIN + c) * 9 + kk];
            float s = sw2[oc];
            float q = rintf(w / s);
            q = fminf(fmaxf(q, -64.f), 63.f);
            v = q * s;
        }
        g_w2q[j] = v;
    }
}

// ---------------- conv1: HMMA, occ 2, W reg-prefetch -------------------------
// CTA: 1 output row y x 128 px x 64 oc. 256 thr = 8 warps.
// Warp: mrow=(warp&3)*32 (px), ncol=(warp>>2)*32 (oc) -> 32px x 32oc.
__global__ __launch_bounds__(256, 2)
void conv1_mma_kernel(const float* __restrict__ x,
                      const float* __restrict__ sw1,
                      const float* __restrict__ b1,
                      const float* __restrict__ alpha1,
                      const float* __restrict__ sa1)
{
    extern __shared__ unsigned char sm[];
    const uint32_t sa_base = smem_u32(sm);
    const uint32_t sw_base = sa_base + SM_W;
    float* s_prm = (float*)(sm + SM_P);

    const int tid  = threadIdx.x;
    const int lane = tid & 31;
    const int warp = tid >> 5;
    const int mrow = (warp & 3) * 32;
    const int ncol = (warp >> 2) * 32;

    const int bid = blockIdx.x;           // 8n * 256y * 2xt = 4096
    const int x0  = (bid & 1) * 128;
    const int y   = (bid >> 1) & 255;
    const int n   = bid >> 9;

    // ---- params ----
    if (tid < 256) {
        int a = tid >> 6, oc = tid & 63;
        const float* src = (a == 0) ? sw1 : (a == 1) ? b1 : (a == 2) ? alpha1 : sa1;
        s_prm[a * 64 + oc] = src[oc];
    }
    // ---- A: 3 image rows (y-1..y+1), exact fp16 2-term split, SW128 --------
    for (int idx = tid; idx < 3 * 130 * 64; idx += 256) {
        int j    = idx % 130;
        int rest = idx / 130;
        int ir   = rest % 3;
        int c    = rest / 3;
        int gy   = y + ir - 1;
        int gx   = x0 - 1 + j;
        float v = 0.f;
        if ((unsigned)gy < 256u && (unsigned)gx < 256u)
            v = x[(((n * 64 + c) * 256 + gy) << 8) + gx];
        __half hi = __float2half_rn(v);
        __half lo = __float2half_rn(v - __half2float(hi));
        uint32_t off = (uint32_t)ir * A_IR + (uint32_t)j * 128u
                     + (((uint32_t)c * 2u) ^ (((uint32_t)(j & 7)) << 4));
        *(__half*)(sm + off)           = hi;
        *(__half*)(sm + A_TERM3 + off) = lo;
    }

    // ---- W prefetch tap 0 into registers ----
    const uint4* wsrc = reinterpret_cast<const uint4*>(g_w1h);
    uint4* wdst = reinterpret_cast<uint4*>(sm + SM_W);
    uint4 wr0 = wsrc[tid * 2];
    uint4 wr1 = wsrc[tid * 2 + 1];

    float acc[2][4][4];
    #pragma unroll
    for (int a = 0; a < 2; ++a)
        #pragma unroll
        for (int b = 0; b < 4; ++b)
            #pragma unroll
            for (int c = 0; c < 4; ++c) acc[a][b][c] = 0.f;

    const uint32_t arow  = lane & 15;
    const uint32_t ahalf = (lane >> 4) * 16;

    int kh = 0, kw = 0;
    #pragma unroll 1
    for (int tap = 0; tap < 9; ++tap) {
        if (tap) __syncthreads();          // prev tap's B ldsm complete
        wdst[tid * 2]     = wr0;
        wdst[tid * 2 + 1] = wr1;
        if (tap < 8) {                     // prefetch next tap (hidden by MMAs)
            wr0 = wsrc[(tap + 1) * 512 + tid * 2];
            wr1 = wsrc[(tap + 1) * 512 + tid * 2 + 1];
        }
        __syncthreads();                   // W ready (tap0: also A+params)

        // ---- B fragments ----
        uint32_t bf[4][4][2];
        #pragma unroll
        for (int k = 0; k < 4; ++k)
            #pragma unroll
            for (int nb = 0; nb < 4; ++nb) {
                uint32_t row = k * 16 + arow;
                ldsm2t(bf[k][nb][0], bf[k][nb][1],
                       sw_base + row * 128u
                               + (((uint32_t)(ncol + nb * 8) * 2u) ^ ((row & 7u) << 4)));
            }
        // ---- A fragments + MMAs (both split terms into same acc) ----
        #pragma unroll
        for (int t = 0; t < 2; ++t) {
            #pragma unroll
            for (int mb = 0; mb < 2; ++mb) {
                uint32_t row  = (uint32_t)(mrow + mb * 16 + kw) + arow;
                uint32_t base = sa_base + (uint32_t)t * A_TERM3
                              + (uint32_t)kh * A_IR + row * 128u;
                uint32_t xr   = (row & 7u) << 4;
                uint32_t af[4][4];
                #pragma unroll
                for (int k = 0; k < 4; ++k)
                    ldsm4(af[k], base + ((ahalf + (uint32_t)k * 32u) ^ xr));
                #pragma unroll
                for (int k = 0; k < 4; ++k)
                    #pragma unroll
                    for (int nb = 0; nb < 4; ++nb)
                        mma16816(acc[mb][nb], af[k], bf[k][nb]);
            }
        }
        if (++kw == 3) { kw = 0; ++kh; }
    }

    // ---- epilogue: scale + bias + PReLU + act fake-quant -> g_h ------------
    #pragma unroll
    for (int nb = 0; nb < 4; ++nb)
        #pragma unroll
        for (int par = 0; par < 2; ++par) {
            int oc = ncol + nb * 8 + ((lane & 3) << 1) + par;
            float sw = s_prm[oc], bb = s_prm[64 + oc];
            float aa = s_prm[128 + oc], ss = s_prm[192 + oc];
            float rs = 1.0f / ss;
            #pragma unroll
            for (int mb = 0; mb < 2; ++mb)
                #pragma unroll
                for (int rh = 0; rh < 2; ++rh) {
                    int j  = mrow + mb * 16 + (lane >> 2) + rh * 8;
                    float v  = acc[mb][nb][rh * 2 + par] * sw + bb;
                    float pv = (v >= 0.f) ? v : aa * v;
                    float q  = rintf(pv * rs);
                    q = fminf(fmaxf(q, -64.f), 63.f);
                    g_h[(((n * 64 + oc) * 256 + y) << 8) + x0 + j] = q * ss;
                }
        }
}

// ---------------- conv2: fp32 FFMA2 (proven R4 kernel, unchanged) -----------
#define TH2   8
#define T2W   128
#define CC2   4
#define P2R   10
#define P2CW  130
#define P2W   131

__global__ __launch_bounds__(128, 6)
void conv2_kernel(const float* __restrict__ b2,
                  const float* __restrict__ alpha2,
                  const float* __restrict__ sa2,
                  float* __restrict__ out)
{
    __shared__ __align__(16) float s_in[CC2 * P2R * P2W];
    __shared__ __align__(16) float s_w2[CC2 * 9 * 4];

    const int tid = threadIdx.x;
    const int bid = blockIdx.x;
    const int tx  = bid & 1;
    const int ty  = (bid >> 1) & 31;
    const int n   = bid >> 6;
    const int x0  = tx * T2W;
    const int y0  = ty * TH2;

    const int r    = tid & 7;
    const int g    = (tid >> 3) & 3;
    const int warp = tid >> 5;
    const int cb   = warp * 32 + g * 8;

    unsigned long long acc[2][8];
    #pragma unroll
    for (int i = 0; i < 2; ++i)
        #pragma unroll
        for (int j = 0; j < 8; ++j) acc[i][j] = 0ULL;

    for (int c0 = 0; c0 < CIN; c0 += CC2) {
        __syncthreads();
        for (int idx = tid; idx < CC2 * P2R * P2CW; idx += 128) {
            int c   = idx / (P2R * P2CW);
            int rem = idx - c * (P2R * P2CW);
            int row = rem / P2CW;
            int col = rem - row * P2CW;
            int gy  = y0 + row - 1;
            int gx  = x0 + col - 1;
            float v = 0.f;
            if ((unsigned)gy < 256u && (unsigned)gx < 256u)
                v = g_h[(((n * CIN + c0 + c) * 256 + gy) << 8) + gx];
            s_in[(c * P2R + row) * P2W + col] = v;
        }
        for (int idx = tid; idx < CC2 * 9 * 4; idx += 128)
            s_w2[idx] = g_w2q[c0 * 9 * 4 + idx];
        __syncthreads();

        #pragma unroll 1
        for (int c = 0; c < CC2; ++c) {
            #pragma unroll
            for (int kh = 0; kh < 3; ++kh) {
                const float* rowp = &s_in[(c * P2R + r + kh) * P2W + cb];
                unsigned long long v2[10];
                #pragma unroll
                for (int i = 0; i < 10; ++i) {
                    unsigned int u = __float_as_uint(rowp[i]);
                    asm("mov.b64 %0, {%1, %1};" : "=l"(v2[i]) : "r"(u));
                }
                #pragma unroll
                for (int kw = 0; kw < 3; ++kw) {
                    const unsigned long long* wp = (const unsigned long long*)
                        &s_w2[(c * 9 + kh * 3 + kw) << 2];
                    unsigned long long w0 = wp[0];
                    unsigned long long w1 = wp[1];
                    #pragma unroll
                    for (int px = 0; px < 8; ++px) {
                        asm("fma.rn.f32x2 %0, %1, %2, %0;"
                            : "+l"(acc[0][px]) : "l"(w0), "l"(v2[px + kw]));
                        asm("fma.rn.f32x2 %0, %1, %2, %0;"
                            : "+l"(acc[1][px]) : "l"(w1), "l"(v2[px + kw]));
                    }
                }
            }
        }
    }

    const int gy = y0 + r;
    const int gx = x0 + cb;
    #pragma unroll
    for (int cp = 0; cp < 2; ++cp) {
        float lo[8], hi[8];
        #pragma unroll
        for (int px = 0; px < 8; ++px) {
            unsigned int a, b;
            asm("mov.b64 {%0, %1}, %2;" : "=r"(a), "=r"(b) : "l"(acc[cp][px]));
            lo[px] = __uint_as_float(a);
            hi[px] = __uint_as_float(b);
        }
        #pragma unroll
        for (int half = 0; half < 2; ++half) {
            int oc = (cp << 1) + half;
            if (oc >= 3) continue;
            const float* v = half ? hi : lo;
            float bb = b2[oc], aa = alpha2[oc], ss = sa2[oc];
            float o[8];
            #pragma unroll
            for (int i = 0; i < 8; ++i) {
                float yv = v[i] + bb;
                float pv = (yv >= 0.f) ? yv : aa * yv;
                float q = rintf(pv / ss);
                q = fminf(fmaxf(q, -64.f), 63.f);
                o[i] = q * ss;
            }
            float4* p4 = reinterpret_cast<float4*>(
                &out[(((n * 3 + oc) * 256 + gy) << 8) + gx]);
            p4[0] = make_float4(o[0], o[1], o[2], o[3]);
            p4[1] = make_float4(o[4], o[5], o[6], o[7]);
        }
    }
}

// ---------------------------------------------------------------------------
extern "C" void kernel_launch(void* const* d_in, const int* in_sizes, int n_in,
                              void* d_out, int out_size)
{
    const float* x      = (const float*)d_in[0];
    const float* w1     = (const float*)d_in[1];
    const float* b1     = (const float*)d_in[2];
    const float* w2     = (const float*)d_in[3];
    const float* b2     = (const float*)d_in[4];
    const float* alpha1 = (const float*)d_in[5];
    const float* alpha2 = (const float*)d_in[6];
    const float* sw1    = (const float*)d_in[7];
    const float* sw2    = (const float*)d_in[8];
    const float* sa1    = (const float*)d_in[9];
    const float* sa2    = (const float*)d_in[10];
    float* out = (float*)d_out;

    cudaFuncSetAttribute(conv1_mma_kernel,
                         cudaFuncAttributeMaxDynamicSharedMemorySize, SMEM1);

    prequant_kernel<<<(9 * 64 * 64 + 64 * 9 * 4 + 255) / 256, 256>>>(w1, sw1, w2, sw2);
    conv1_mma_kernel<<<NB * 256 * 2, 256, SMEM1>>>(x, sw1, b1, alpha1, sa1);
    conv2_kernel<<<NB * 32 * 2, 128>>>(b2, alpha2, sa2, out);
}

// round 10
// speedup vs baseline: 1.8568x; 1.5903x over previous
#include <cuda_runtime.h>
#include <cuda_fp16.h>
#include <cstdint>

// ---------------------------------------------------------------------------
// R10: R6 conv1 skeleton (best known, 4 warps/SMSP) + cp.async ping-pong W
//      (zero-register prefetch), 11 barriers instead of 27.
//      conv2 = proven R4 fp32 FFMA2 kernel.
// ---------------------------------------------------------------------------

#define IMG   256
#define NB    8
#define CIN   64

__device__ float  g_h[NB * CIN * IMG * IMG];
__device__ __half g_w1h[9 * 64 * 64];          // [tap][c][oc] linear (R6 layout)
__device__ float  g_w2q[CIN * 9 * 4];

__device__ __forceinline__ uint32_t smem_u32(const void* p) {
    uint32_t a;
    asm("{ .reg .u64 t; cvta.to.shared.u64 t, %1; cvt.u32.u64 %0, t; }"
        : "=r"(a) : "l"(p));
    return a;
}
__device__ __forceinline__ void ldsm4(uint32_t* r, uint32_t addr) {
    asm volatile("ldmatrix.sync.aligned.m8n8.x4.shared.b16 {%0,%1,%2,%3}, [%4];"
        : "=r"(r[0]), "=r"(r[1]), "=r"(r[2]), "=r"(r[3]) : "r"(addr));
}
__device__ __forceinline__ void ldsm2t(uint32_t& r0, uint32_t& r1, uint32_t addr) {
    asm volatile("ldmatrix.sync.aligned.m8n8.x2.trans.shared.b16 {%0,%1}, [%2];"
        : "=r"(r0), "=r"(r1) : "r"(addr));
}
__device__ __forceinline__ void mma16816(float* c, const uint32_t* a, const uint32_t* b) {
    asm volatile("mma.sync.aligned.m16n8k16.row.col.f32.f16.f16.f32 "
        "{%0,%1,%2,%3}, {%4,%5,%6,%7}, {%8,%9}, {%0,%1,%2,%3};"
        : "+f"(c[0]), "+f"(c[1]), "+f"(c[2]), "+f"(c[3])
        : "r"(a[0]), "r"(a[1]), "r"(a[2]), "r"(a[3]), "r"(b[0]), "r"(b[1]));
}
__device__ __forceinline__ void cp16(uint32_t dst, const void* src) {
    asm volatile("cp.async.cg.shared.global [%0], [%1], 16;"
        :: "r"(dst), "l"(src));
}
#define CP_COMMIT() asm volatile("cp.async.commit_group;" ::: "memory")
#define CP_WAIT0()  asm volatile("cp.async.wait_group 0;"  ::: "memory")

// dynamic smem layout (16B-aligned offsets):
//   A: 2 terms x 130 rows x 144B = 37440
//   W: 2 bufs x (64 rows x 144B) = 18432
//   params: 1024
#define A_TERMB 18720u
#define W_OFF   37440u
#define W_BUF   9216u
#define P_OFF   (W_OFF + 2u * W_BUF)   // 55872
#define SMEM1   (P_OFF + 1024u)        // 56896 -> occ 2 (113.8KB)

// ---------------- prequant (one-shot) ---------------------------------------
__global__ void prequant_kernel(const float* __restrict__ w1,
                                const float* __restrict__ sw1,
                                const float* __restrict__ w2,
                                const float* __restrict__ sw2)
{
    int idx = blockIdx.x * 256 + threadIdx.x;
    if (idx < 9 * 64 * 64) {
        int oc  = idx & 63;
        int c   = (idx >> 6) & 63;
        int tap = idx >> 12;
        float w = w1[(oc * 64 + c) * 9 + tap];
        float s = sw1[oc];
        float q = rintf(w / s);
        q = fminf(fmaxf(q, -64.f), 63.f);
        g_w1h[idx] = __float2half_rn(q);        // exact 7-bit integer
    } else if (idx < 9 * 64 * 64 + 64 * 9 * 4) {
        int j  = idx - 9 * 64 * 64;
        int oc = j & 3;
        int k  = j >> 2;
        int c  = k / 9;
        int kk = k - c * 9;
        float v = 0.f;
        if (oc < 3) {
            float w = w2[(oc * CIN + c) * 9 + kk];
            float s = sw2[oc];
            float q = rintf(w / s);
            q = fminf(fmaxf(q, -64.f), 63.f);
            v = q * s;
        }
        g_w2q[j] = v;
    }
}

// ---------------- conv1: HMMA (R6 structure + cp.async W pipeline) ----------
// CTA = 128-px row strip (n, y, x0), 64 oc. 256 thr = 8 warps.
// Warp tile: 32 px (mrow=(w&3)*32) x 32 oc (ncol=(w>>2)*32).
__global__ __launch_bounds__(256, 2)
void conv1_mma_kernel(const float* __restrict__ x,
                      const float* __restrict__ sw1,
                      const float* __restrict__ b1,
                      const float* __restrict__ alpha1,
                      const float* __restrict__ sa1)
{
    extern __shared__ unsigned char sm[];
    __half* s_a  = (__half*)sm;
    float*  s_prm = (float*)(sm + P_OFF);
    const uint32_t sa_base = smem_u32(sm);
    const uint32_t sw_base = sa_base + W_OFF;

    const int tid  = threadIdx.x;
    const int lane = tid & 31;
    const int warp = tid >> 5;
    const int mrow = (warp & 3) * 32;
    const int ncol = (warp >> 2) * 32;

    const int bid = blockIdx.x;          // 8n * 256y * 2xt = 4096
    const int x0  = (bid & 1) * 128;
    const int y   = (bid >> 1) & 255;
    const int n   = bid >> 9;

    // ---- prefetch W tap 0 via cp.async (overlaps params + A build) ----
    {
        const char* src = (const char*)g_w1h;   // tap 0 at offset 0
        uint32_t dst = sw_base + (uint32_t)(tid >> 3) * 144u
                     + (uint32_t)(tid & 7) * 16u;
        cp16(dst, src + tid * 16);
        cp16(dst + (256 >> 3) * 144u, src + (tid + 256) * 16);
        CP_COMMIT();
    }

    if (tid < 256) {
        int a = tid >> 6, oc = tid & 63;
        const float* src = (a == 0) ? sw1 : (a == 1) ? b1 : (a == 2) ? alpha1 : sa1;
        s_prm[a * 64 + oc] = src[oc];
    }

    float acc[2][4][4];
    #pragma unroll
    for (int i = 0; i < 2; ++i)
        #pragma unroll
        for (int j = 0; j < 4; ++j)
            #pragma unroll
            for (int k = 0; k < 4; ++k) acc[i][j][k] = 0.f;

    const uint32_t arow  = lane & 15;
    const uint32_t ahalf = (lane >> 4) * 16;

    for (int s = 0; s < 3; ++s) {
        const int gy = y + s - 1;
        const bool row_ok = (unsigned)gy < 256u;
        if (s) __syncthreads();            // prior tap's A reads done
        // ---- build exact fp16 2-term split strip (144B rows, as R6) ----
        for (int idx = tid; idx < 64 * 130; idx += 256) {
            int c = idx / 130;
            int j = idx - c * 130;
            int gx = x0 - 1 + j;
            float v = 0.f;
            if (row_ok && (unsigned)gx < 256u)
                v = x[(((n * 64 + c) * 256 + gy) << 8) + gx];
            __half hi = __float2half_rn(v);
            __half lo = __float2half_rn(v - __half2float(hi));
            s_a[j * 72 + c]             = hi;
            s_a[9360 + j * 72 + c]      = lo;   // 9360 halves = A_TERMB bytes
        }

        for (int kw = 0; kw < 3; ++kw) {
            const int tap = s * 3 + kw;
            CP_WAIT0();                    // W[tap] landed in buf[tap&1]
            __syncthreads();               // W (+A on kw==0) visible to all
            if (tap < 8) {                 // prefetch next tap into other buf
                const char* src = (const char*)g_w1h + (tap + 1) * 8192;
                uint32_t dst = sw_base + ((uint32_t)(tap + 1) & 1u) * W_BUF
                             + (uint32_t)(tid >> 3) * 144u
                             + (uint32_t)(tid & 7) * 16u;
                cp16(dst, src + tid * 16);
                cp16(dst + (256 >> 3) * 144u, src + (tid + 256) * 16);
                CP_COMMIT();
            }
            const uint32_t swb = sw_base + ((uint32_t)tap & 1u) * W_BUF;

            // ---- B fragments ----
            uint32_t bf[4][4][2];
            #pragma unroll
            for (int k = 0; k < 4; ++k)
                #pragma unroll
                for (int nb = 0; nb < 4; ++nb)
                    ldsm2t(bf[k][nb][0], bf[k][nb][1],
                           swb + (uint32_t)(k * 16 + arow) * 144u
                               + (uint32_t)(ncol + nb * 8) * 2u);
            // ---- A fragments + MMAs (both split terms into same acc) ----
            #pragma unroll
            for (int t = 0; t < 2; ++t) {
                #pragma unroll
                for (int mb = 0; mb < 2; ++mb) {
                    uint32_t abase = sa_base + (uint32_t)t * A_TERMB
                                   + (uint32_t)(mrow + mb * 16 + arow + kw) * 144u
                                   + ahalf;
                    uint32_t af[4][4];
                    #pragma unroll
                    for (int k = 0; k < 4; ++k)
                        ldsm4(af[k], abase + (uint32_t)k * 32u);
                    #pragma unroll
                    for (int k = 0; k < 4; ++k)
                        #pragma unroll
                        for (int nb = 0; nb < 4; ++nb)
                            mma16816(acc[mb][nb], af[k], bf[k][nb]);
                }
            }
        }
    }

    // ---- epilogue: scale + bias + PReLU + act fake-quant -> g_h ------------
    #pragma unroll
    for (int mb = 0; mb < 2; ++mb)
        #pragma unroll
        for (int nb = 0; nb < 4; ++nb)
            #pragma unroll
            for (int rg = 0; rg < 4; ++rg) {
                int j  = mrow + mb * 16 + (lane >> 2) + (rg >> 1) * 8;
                int oc = ncol + nb * 8 + ((lane & 3) << 1) + (rg & 1);
                float v  = acc[mb][nb][rg] * s_prm[oc] + s_prm[64 + oc];
                float pv = (v >= 0.f) ? v : s_prm[128 + oc] * v;
                float ss = s_prm[192 + oc];
                float q  = rintf(pv / ss);
                q = fminf(fmaxf(q, -64.f), 63.f);
                g_h[(((n * 64 + oc) * 256 + y) << 8) + x0 + j] = q * ss;
            }
}

// ---------------- conv2: fp32 FFMA2 (proven R4 kernel, unchanged) -----------
#define TH2   8
#define T2W   128
#define CC2   4
#define P2R   10
#define P2CW  130
#define P2W   131

__global__ __launch_bounds__(128, 6)
void conv2_kernel(const float* __restrict__ b2,
                  const float* __restrict__ alpha2,
                  const float* __restrict__ sa2,
                  float* __restrict__ out)
{
    __shared__ __align__(16) float s_in[CC2 * P2R * P2W];
    __shared__ __align__(16) float s_w2[CC2 * 9 * 4];

    const int tid = threadIdx.x;
    const int bid = blockIdx.x;
    const int tx  = bid & 1;
    const int ty  = (bid >> 1) & 31;
    const int n   = bid >> 6;
    const int x0  = tx * T2W;
    const int y0  = ty * TH2;

    const int r    = tid & 7;
    const int g    = (tid >> 3) & 3;
    const int warp = tid >> 5;
    const int cb   = warp * 32 + g * 8;

    unsigned long long acc[2][8];
    #pragma unroll
    for (int i = 0; i < 2; ++i)
        #pragma unroll
        for (int j = 0; j < 8; ++j) acc[i][j] = 0ULL;

    for (int c0 = 0; c0 < CIN; c0 += CC2) {
        __syncthreads();
        for (int idx = tid; idx < CC2 * P2R * P2CW; idx += 128) {
            int c   = idx / (P2R * P2CW);
            int rem = idx - c * (P2R * P2CW);
            int row = rem / P2CW;
            int col = rem - row * P2CW;
            int gy  = y0 + row - 1;
            int gx  = x0 + col - 1;
            float v = 0.f;
            if ((unsigned)gy < 256u && (unsigned)gx < 256u)
                v = g_h[(((n * CIN + c0 + c) * 256 + gy) << 8) + gx];
            s_in[(c * P2R + row) * P2W + col] = v;
        }
        for (int idx = tid; idx < CC2 * 9 * 4; idx += 128)
            s_w2[idx] = g_w2q[c0 * 9 * 4 + idx];
        __syncthreads();

        #pragma unroll 1
        for (int c = 0; c < CC2; ++c) {
            #pragma unroll
            for (int kh = 0; kh < 3; ++kh) {
                const float* rowp = &s_in[(c * P2R + r + kh) * P2W + cb];
                unsigned long long v2[10];
                #pragma unroll
                for (int i = 0; i < 10; ++i) {
                    unsigned int u = __float_as_uint(rowp[i]);
                    asm("mov.b64 %0, {%1, %1};" : "=l"(v2[i]) : "r"(u));
                }
                #pragma unroll
                for (int kw = 0; kw < 3; ++kw) {
                    const unsigned long long* wp = (const unsigned long long*)
                        &s_w2[(c * 9 + kh * 3 + kw) << 2];
                    unsigned long long w0 = wp[0];
                    unsigned long long w1 = wp[1];
                    #pragma unroll
                    for (int px = 0; px < 8; ++px) {
                        asm("fma.rn.f32x2 %0, %1, %2, %0;"
                            : "+l"(acc[0][px]) : "l"(w0), "l"(v2[px + kw]));
                        asm("fma.rn.f32x2 %0, %1, %2, %0;"
                            : "+l"(acc[1][px]) : "l"(w1), "l"(v2[px + kw]));
                    }
                }
            }
        }
    }

    const int gy = y0 + r;
    const int gx = x0 + cb;
    #pragma unroll
    for (int cp = 0; cp < 2; ++cp) {
        float lo[8], hi[8];
        #pragma unroll
        for (int px = 0; px < 8; ++px) {
            unsigned int a, b;
            asm("mov.b64 {%0, %1}, %2;" : "=r"(a), "=r"(b) : "l"(acc[cp][px]));
            lo[px] = __uint_as_float(a);
            hi[px] = __uint_as_float(b);
        }
        #pragma unroll
        for (int half = 0; half < 2; ++half) {
            int oc = (cp << 1) + half;
            if (oc >= 3) continue;
            const float* v = half ? hi : lo;
            float bb = b2[oc], aa = alpha2[oc], ss = sa2[oc];
            float o[8];
            #pragma unroll
            for (int i = 0; i < 8; ++i) {
                float yv = v[i] + bb;
                float pv = (yv >= 0.f) ? yv : aa * yv;
                float q = rintf(pv / ss);
                q = fminf(fmaxf(q, -64.f), 63.f);
                o[i] = q * ss;
            }
            float4* p4 = reinterpret_cast<float4*>(
                &out[(((n * 3 + oc) * 256 + gy) << 8) + gx]);
            p4[0] = make_float4(o[0], o[1], o[2], o[3]);
            p4[1] = make_float4(o[4], o[5], o[6], o[7]);
        }
    }
}

// ---------------------------------------------------------------------------
extern "C" void kernel_launch(void* const* d_in, const int* in_sizes, int n_in,
                              void* d_out, int out_size)
{
    const float* x      = (const float*)d_in[0];
    const float* w1     = (const float*)d_in[1];
    const float* b1     = (const float*)d_in[2];
    const float* w2     = (const float*)d_in[3];
    const float* b2     = (const float*)d_in[4];
    const float* alpha1 = (const float*)d_in[5];
    const float* alpha2 = (const float*)d_in[6];
    const float* sw1    = (const float*)d_in[7];
    const float* sw2    = (const float*)d_in[8];
    const float* sa1    = (const float*)d_in[9];
    const float* sa2    = (const float*)d_in[10];
    float* out = (float*)d_out;

    cudaFuncSetAttribute(conv1_mma_kernel,
                         cudaFuncAttributeMaxDynamicSharedMemorySize, SMEM1);

    prequant_kernel<<<(9 * 64 * 64 + 64 * 9 * 4 + 255) / 256, 256>>>(w1, sw1, w2, sw2);
    conv1_mma_kernel<<<NB * 256 * 2, 256, SMEM1>>>(x, sw1, b1, alpha1, sa1);
    conv2_kernel<<<NB * 32 * 2, 128>>>(b2, alpha2, sa2, out);
}

// round 11
// speedup vs baseline: 2.0184x; 1.0870x over previous
#include <cuda_runtime.h>
#include <cuda_fp16.h>
#include <cstdint>

// ---------------------------------------------------------------------------
// R11: R10 + occupancy-3 conv1. Inner loop restructured (bf reloaded per
//      (t,k), af per (t,k,mb)) to cut live regs ~120 -> ~75 so occ 3 fits
//      (reg cap 85). Accumulation order per accumulator preserved exactly.
//      conv2 = proven R4 fp32 FFMA2 kernel.
// ---------------------------------------------------------------------------

#define IMG   256
#define NB    8
#define CIN   64

__device__ float  g_h[NB * CIN * IMG * IMG];
__device__ __half g_w1h[9 * 64 * 64];          // [tap][c][oc] linear
__device__ float  g_w2q[CIN * 9 * 4];

__device__ __forceinline__ uint32_t smem_u32(const void* p) {
    uint32_t a;
    asm("{ .reg .u64 t; cvta.to.shared.u64 t, %1; cvt.u32.u64 %0, t; }"
        : "=r"(a) : "l"(p));
    return a;
}
__device__ __forceinline__ void ldsm4(uint32_t* r, uint32_t addr) {
    asm volatile("ldmatrix.sync.aligned.m8n8.x4.shared.b16 {%0,%1,%2,%3}, [%4];"
        : "=r"(r[0]), "=r"(r[1]), "=r"(r[2]), "=r"(r[3]) : "r"(addr));
}
__device__ __forceinline__ void ldsm2t(uint32_t& r0, uint32_t& r1, uint32_t addr) {
    asm volatile("ldmatrix.sync.aligned.m8n8.x2.trans.shared.b16 {%0,%1}, [%2];"
        : "=r"(r0), "=r"(r1) : "r"(addr));
}
__device__ __forceinline__ void mma16816(float* c, const uint32_t* a, const uint32_t* b) {
    asm volatile("mma.sync.aligned.m16n8k16.row.col.f32.f16.f16.f32 "
        "{%0,%1,%2,%3}, {%4,%5,%6,%7}, {%8,%9}, {%0,%1,%2,%3};"
        : "+f"(c[0]), "+f"(c[1]), "+f"(c[2]), "+f"(c[3])
        : "r"(a[0]), "r"(a[1]), "r"(a[2]), "r"(a[3]), "r"(b[0]), "r"(b[1]));
}
__device__ __forceinline__ void cp16(uint32_t dst, const void* src) {
    asm volatile("cp.async.cg.shared.global [%0], [%1], 16;"
        :: "r"(dst), "l"(src));
}
#define CP_COMMIT() asm volatile("cp.async.commit_group;" ::: "memory")
#define CP_WAIT0()  asm volatile("cp.async.wait_group 0;"  ::: "memory")

// dynamic smem layout:
#define A_TERMB 18720u                 // 130 rows x 144B per split term
#define W_OFF   37440u
#define W_BUF   9216u
#define P_OFF   (W_OFF + 2u * W_BUF)   // 55872
#define SMEM1   (P_OFF + 1024u)        // 56896 -> occ 3 (170.7KB)

// ---------------- prequant (one-shot) ---------------------------------------
__global__ void prequant_kernel(const float* __restrict__ w1,
                                const float* __restrict__ sw1,
                                const float* __restrict__ w2,
                                const float* __restrict__ sw2)
{
    int idx = blockIdx.x * 256 + threadIdx.x;
    if (idx < 9 * 64 * 64) {
        int oc  = idx & 63;
        int c   = (idx >> 6) & 63;
        int tap = idx >> 12;
        float w = w1[(oc * 64 + c) * 9 + tap];
        float s = sw1[oc];
        float q = rintf(w / s);
        q = fminf(fmaxf(q, -64.f), 63.f);
        g_w1h[idx] = __float2half_rn(q);        // exact 7-bit integer
    } else if (idx < 9 * 64 * 64 + 64 * 9 * 4) {
        int j  = idx - 9 * 64 * 64;
        int oc = j & 3;
        int k  = j >> 2;
        int c  = k / 9;
        int kk = k - c * 9;
        float v = 0.f;
        if (oc < 3) {
            float w = w2[(oc * CIN + c) * 9 + kk];
            float s = sw2[oc];
            float q = rintf(w / s);
            q = fminf(fmaxf(q, -64.f), 63.f);
            v = q * s;
        }
        g_w2q[j] = v;
    }
}

// ---------------- conv1: HMMA, occ 3, low-reg inner loop ---------------------
// CTA = 128-px row strip (n, y, x0), 64 oc. 256 thr = 8 warps.
// Warp tile: 32 px (mrow=(w&3)*32) x 32 oc (ncol=(w>>2)*32).
__global__ __launch_bounds__(256, 3)
void conv1_mma_kernel(const float* __restrict__ x,
                      const float* __restrict__ sw1,
                      const float* __restrict__ b1,
                      const float* __restrict__ alpha1,
                      const float* __restrict__ sa1)
{
    extern __shared__ unsigned char sm[];
    __half* s_a   = (__half*)sm;
    float*  s_prm = (float*)(sm + P_OFF);
    const uint32_t sa_base = smem_u32(sm);
    const uint32_t sw_base = sa_base + W_OFF;

    const int tid  = threadIdx.x;
    const int lane = tid & 31;
    const int warp = tid >> 5;
    const int mrow = (warp & 3) * 32;
    const int ncol = (warp >> 2) * 32;

    const int bid = blockIdx.x;          // 8n * 256y * 2xt = 4096
    const int x0  = (bid & 1) * 128;
    const int y   = (bid >> 1) & 255;
    const int n   = bid >> 9;

    // ---- prefetch W tap 0 via cp.async (overlaps params + A build) ----
    {
        const char* src = (const char*)g_w1h;
        uint32_t dst = sw_base + (uint32_t)(tid >> 3) * 144u
                     + (uint32_t)(tid & 7) * 16u;
        cp16(dst, src + tid * 16);
        cp16(dst + (256 >> 3) * 144u, src + (tid + 256) * 16);
        CP_COMMIT();
    }

    if (tid < 256) {
        int a = tid >> 6, oc = tid & 63;
        const float* src = (a == 0) ? sw1 : (a == 1) ? b1 : (a == 2) ? alpha1 : sa1;
        s_prm[a * 64 + oc] = src[oc];
    }

    float acc[2][4][4];
    #pragma unroll
    for (int i = 0; i < 2; ++i)
        #pragma unroll
        for (int j = 0; j < 4; ++j)
            #pragma unroll
            for (int k = 0; k < 4; ++k) acc[i][j][k] = 0.f;

    const uint32_t arow  = lane & 15;
    const uint32_t ahalf = (lane >> 4) * 16;

    for (int s = 0; s < 3; ++s) {
        const int gy = y + s - 1;
        const bool row_ok = (unsigned)gy < 256u;
        if (s) __syncthreads();            // prior tap's A reads done
        // ---- build exact fp16 2-term split strip (144B rows) ----
        for (int idx = tid; idx < 64 * 130; idx += 256) {
            int c = idx / 130;
            int j = idx - c * 130;
            int gx = x0 - 1 + j;
            float v = 0.f;
            if (row_ok && (unsigned)gx < 256u)
                v = x[(((n * 64 + c) * 256 + gy) << 8) + gx];
            __half hi = __float2half_rn(v);
            __half lo = __float2half_rn(v - __half2float(hi));
            s_a[j * 72 + c]        = hi;
            s_a[9360 + j * 72 + c] = lo;   // 9360 halves = A_TERMB bytes
        }

        for (int kw = 0; kw < 3; ++kw) {
            const int tap = s * 3 + kw;
            CP_WAIT0();                    // W[tap] landed in buf[tap&1]
            __syncthreads();               // W (+A on kw==0) visible to all
            if (tap < 8) {                 // prefetch next tap into other buf
                const char* src = (const char*)g_w1h + (tap + 1) * 8192;
                uint32_t dst = sw_base + ((uint32_t)(tap + 1) & 1u) * W_BUF
                             + (uint32_t)(tid >> 3) * 144u
                             + (uint32_t)(tid & 7) * 16u;
                cp16(dst, src + tid * 16);
                cp16(dst + (256 >> 3) * 144u, src + (tid + 256) * 16);
                CP_COMMIT();
            }
            const uint32_t swb = sw_base + ((uint32_t)tap & 1u) * W_BUF;

            // ---- low-register MMA stream ----
            // per-accumulator order: t0:k0..k3, t1:k0..k3  (== R10 exactly)
            #pragma unroll
            for (int t = 0; t < 2; ++t) {
                #pragma unroll
                for (int k = 0; k < 4; ++k) {
                    uint32_t bf[4][2];
                    #pragma unroll
                    for (int nb = 0; nb < 4; ++nb)
                        ldsm2t(bf[nb][0], bf[nb][1],
                               swb + (uint32_t)(k * 16 + arow) * 144u
                                   + (uint32_t)(ncol + nb * 8) * 2u);
                    #pragma unroll
                    for (int mb = 0; mb < 2; ++mb) {
                        uint32_t af[4];
                        ldsm4(af, sa_base + (uint32_t)t * A_TERMB
                                 + (uint32_t)(mrow + mb * 16 + arow + kw) * 144u
                                 + ahalf + (uint32_t)k * 32u);
                        #pragma unroll
                        for (int nb = 0; nb < 4; ++nb)
                            mma16816(acc[mb][nb], af, bf[nb]);
                    }
                }
            }
        }
    }

    // ---- epilogue: scale + bias + PReLU + act fake-quant -> g_h ------------
    #pragma unroll
    for (int mb = 0; mb < 2; ++mb)
        #pragma unroll
        for (int nb = 0; nb < 4; ++nb)
            #pragma unroll
            for (int rg = 0; rg < 4; ++rg) {
                int j  = mrow + mb * 16 + (lane >> 2) + (rg >> 1) * 8;
                int oc = ncol + nb * 8 + ((lane & 3) << 1) + (rg & 1);
                float v  = acc[mb][nb][rg] * s_prm[oc] + s_prm[64 + oc];
                float pv = (v >= 0.f) ? v : s_prm[128 + oc] * v;
                float ss = s_prm[192 + oc];
                float q  = rintf(pv / ss);
                q = fminf(fmaxf(q, -64.f), 63.f);
                g_h[(((n * 64 + oc) * 256 + y) << 8) + x0 + j] = q * ss;
            }
}

// ---------------- conv2: fp32 FFMA2 (proven R4 kernel, unchanged) -----------
#define TH2   8
#define T2W   128
#define CC2   4
#define P2R   10
#define P2CW  130
#define P2W   131

__global__ __launch_bounds__(128, 6)
void conv2_kernel(const float* __restrict__ b2,
                  const float* __restrict__ alpha2,
                  const float* __restrict__ sa2,
                  float* __restrict__ out)
{
    __shared__ __align__(16) float s_in[CC2 * P2R * P2W];
    __shared__ __align__(16) float s_w2[CC2 * 9 * 4];

    const int tid = threadIdx.x;
    const int bid = blockIdx.x;
    const int tx  = bid & 1;
    const int ty  = (bid >> 1) & 31;
    const int n   = bid >> 6;
    const int x0  = tx * T2W;
    const int y0  = ty * TH2;

    const int r    = tid & 7;
    const int g    = (tid >> 3) & 3;
    const int warp = tid >> 5;
    const int cb   = warp * 32 + g * 8;

    unsigned long long acc[2][8];
    #pragma unroll
    for (int i = 0; i < 2; ++i)
        #pragma unroll
        for (int j = 0; j < 8; ++j) acc[i][j] = 0ULL;

    for (int c0 = 0; c0 < CIN; c0 += CC2) {
        __syncthreads();
        for (int idx = tid; idx < CC2 * P2R * P2CW; idx += 128) {
            int c   = idx / (P2R * P2CW);
            int rem = idx - c * (P2R * P2CW);
            int row = rem / P2CW;
            int col = rem - row * P2CW;
            int gy  = y0 + row - 1;
            int gx  = x0 + col - 1;
            float v = 0.f;
            if ((unsigned)gy < 256u && (unsigned)gx < 256u)
                v = g_h[(((n * CIN + c0 + c) * 256 + gy) << 8) + gx];
            s_in[(c * P2R + row) * P2W + col] = v;
        }
        for (int idx = tid; idx < CC2 * 9 * 4; idx += 128)
            s_w2[idx] = g_w2q[c0 * 9 * 4 + idx];
        __syncthreads();

        #pragma unroll 1
        for (int c = 0; c < CC2; ++c) {
            #pragma unroll
            for (int kh = 0; kh < 3; ++kh) {
                const float* rowp = &s_in[(c * P2R + r + kh) * P2W + cb];
                unsigned long long v2[10];
                #pragma unroll
                for (int i = 0; i < 10; ++i) {
                    unsigned int u = __float_as_uint(rowp[i]);
                    asm("mov.b64 %0, {%1, %1};" : "=l"(v2[i]) : "r"(u));
                }
                #pragma unroll
                for (int kw = 0; kw < 3; ++kw) {
                    const unsigned long long* wp = (const unsigned long long*)
                        &s_w2[(c * 9 + kh * 3 + kw) << 2];
                    unsigned long long w0 = wp[0];
                    unsigned long long w1 = wp[1];
                    #pragma unroll
                    for (int px = 0; px < 8; ++px) {
                        asm("fma.rn.f32x2 %0, %1, %2, %0;"
                            : "+l"(acc[0][px]) : "l"(w0), "l"(v2[px + kw]));
                        asm("fma.rn.f32x2 %0, %1, %2, %0;"
                            : "+l"(acc[1][px]) : "l"(w1), "l"(v2[px + kw]));
                    }
                }
            }
        }
    }

    const int gy = y0 + r;
    const int gx = x0 + cb;
    #pragma unroll
    for (int cp = 0; cp < 2; ++cp) {
        float lo[8], hi[8];
        #pragma unroll
        for (int px = 0; px < 8; ++px) {
            unsigned int a, b;
            asm("mov.b64 {%0, %1}, %2;" : "=r"(a), "=r"(b) : "l"(acc[cp][px]));
            lo[px] = __uint_as_float(a);
            hi[px] = __uint_as_float(b);
        }
        #pragma unroll
        for (int half = 0; half < 2; ++half) {
            int oc = (cp << 1) + half;
            if (oc >= 3) continue;
            const float* v = half ? hi : lo;
            float bb = b2[oc], aa = alpha2[oc], ss = sa2[oc];
            float o[8];
            #pragma unroll
            for (int i = 0; i < 8; ++i) {
                float yv = v[i] + bb;
                float pv = (yv >= 0.f) ? yv : aa * yv;
                float q = rintf(pv / ss);
                q = fminf(fmaxf(q, -64.f), 63.f);
                o[i] = q * ss;
            }
            float4* p4 = reinterpret_cast<float4*>(
                &out[(((n * 3 + oc) * 256 + gy) << 8) + gx]);
            p4[0] = make_float4(o[0], o[1], o[2], o[3]);
            p4[1] = make_float4(o[4], o[5], o[6], o[7]);
        }
    }
}

// ---------------------------------------------------------------------------
extern "C" void kernel_launch(void* const* d_in, const int* in_sizes, int n_in,
                              void* d_out, int out_size)
{
    const float* x      = (const float*)d_in[0];
    const float* w1     = (const float*)d_in[1];
    const float* b1     = (const float*)d_in[2];
    const float* w2     = (const float*)d_in[3];
    const float* b2     = (const float*)d_in[4];
    const float* alpha1 = (const float*)d_in[5];
    const float* alpha2 = (const float*)d_in[6];
    const float* sw1    = (const float*)d_in[7];
    const float* sw2    = (const float*)d_in[8];
    const float* sa1    = (const float*)d_in[9];
    const float* sa2    = (const float*)d_in[10];
    float* out = (float*)d_out;

    cudaFuncSetAttribute(conv1_mma_kernel,
                         cudaFuncAttributeMaxDynamicSharedMemorySize, SMEM1);

    prequant_kernel<<<(9 * 64 * 64 + 64 * 9 * 4 + 255) / 256, 256>>>(w1, sw1, w2, sw2);
    conv1_mma_kernel<<<NB * 256 * 2, 256, SMEM1>>>(x, sw1, b1, alpha1, sa1);
    conv2_kernel<<<NB * 32 * 2, 128>>>(b2, alpha2, sa2, out);
}